// round 7
// baseline (speedup 1.0000x reference)
#include <cuda_runtime.h>
#include <cstdint>

// Problem constants (fixed by the reference)
#define BB 32
#define TT 256
#define NN 1536
#define NI 768

// Fused kernel: 96 FF-producer CTAs + 32 sim CTAs, 384 threads each.
#define TPB    384
#define NPT    4
#define NWARP  (TPB / 32)
#define NPROD  96
#define NTILE  24          // 24 column tiles of 64
#define FCOLS  64

// exp constants, correctly rounded fp32
#define AR0 0.13533528323661270f   // exp(-2)    : rise tau 0.5 (syn0, syn2, FF)
#define AR1 0.60653065971263342f   // exp(-0.5)  : rise tau 2   (syn1)
#define AD0 0.60653065971263342f   // exp(-0.5)  : decay tau 2  (syn0, FF)
#define AD1 0.99004983374916805f   // exp(-0.01) : decay tau 100(syn1)
#define AD2 0.81873075307798186f   // exp(-0.2)  : decay tau 5  (syn2)

// ------------------------- device scratch (statics; no allocs) -------------
__device__ float d_Wsc[NN * NN];             // weights * sf[ct[n]][ct[m]]
__device__ float d_WFsc[NI * NN];            // weights_FF * sfF[ct[m]]
__device__ float d_IF[(size_t)BB * TT * NN]; // FF drive (produced in-kernel)
__device__ int   d_ffcnt[BB * TT];           // input spike counts per (b,t)
__device__ int   d_fflist[BB * TT][NI];      // byte offsets j*NN*4
__device__ int   d_wm[BB][NTILE];            // per-(batch,tile) watermark

// ------------------------- packed f32x2 helpers -----------------------------
typedef unsigned long long u64;
__device__ __forceinline__ u64 pk2(float lo, float hi) {
    u64 r; asm("mov.b64 %0, {%1,%2};" : "=l"(r) : "f"(lo), "f"(hi)); return r;
}
__device__ __forceinline__ void upk2(float& lo, float& hi, u64 v) {
    asm("mov.b64 {%0,%1}, %2;" : "=f"(lo), "=f"(hi) : "l"(v));
}
__device__ __forceinline__ u64 fma2(u64 a, u64 b, u64 c) {
    u64 d; asm("fma.rn.f32x2 %0, %1, %2, %3;" : "=l"(d) : "l"(a), "l"(b), "l"(c));
    return d;
}
__device__ __forceinline__ u64 add2(u64 a, u64 b) {
    u64 d; asm("add.rn.f32x2 %0, %1, %2;" : "=l"(d) : "l"(a), "l"(b)); return d;
}
__device__ __forceinline__ u64 mul2(u64 a, u64 b) {
    u64 d; asm("mul.rn.f32x2 %0, %1, %2;" : "=l"(d) : "l"(a), "l"(b)); return d;
}

// ------------------------- init (per-launch watermark reset) ----------------
__global__ void init_k() {
    ((int*)d_wm)[threadIdx.x] = 0;            // BB*NTILE = 768 ints
}

// ------------------------- weight scaling ----------------------------------
__global__ void scale_k(const float* __restrict__ w, const float* __restrict__ wff,
                        const float* __restrict__ sf, const float* __restrict__ sff,
                        const int* __restrict__ ct) {
    int idx = blockIdx.x * 256 + threadIdx.x;
    if (idx < NN * NN) {
        int n = idx / NN, m = idx % NN;
        d_Wsc[idx] = w[idx] * sf[ct[n] * 2 + ct[m]];
    } else {
        int r = idx - NN * NN;
        if (r < NI * NN) {
            int m = r % NN;
            d_WFsc[r] = wff[r] * sff[ct[m]];   // ct_FF is all zeros -> row 0
        }
    }
}

// ------------------------- FF spike lists (ballot-ordered, byte offsets) ---
__global__ void ffl_k(const float* __restrict__ inp) {
    int bt = blockIdx.x * 4 + (threadIdx.x >> 5); // 4 (b,t) rows per block
    int lane = threadIdx.x & 31;
    const float* row = inp + (size_t)bt * NI;
    int cnt = 0;
    for (int base = 0; base < NI; base += 32) {
        float v = row[base + lane];
        unsigned m = __ballot_sync(0xFFFFFFFFu, v > 0.5f);
        if (v > 0.5f) {
            int p = cnt + __popc(m & ((1u << lane) - 1u));
            d_fflist[bt][p] = (base + lane) * NN * 4;   // byte offset of row
        }
        cnt += __popc(m);
    }
    if (lane == 0) d_ffcnt[bt] = cnt;
}

// ------------------------- fused producer + simulator ------------------------
// blockIdx 0..95  : FF producers. CTA = (tile tau = blk>>2, group g = blk&3).
//   Warp w<8 owns batch g*8+w; lanes cover 64 cols via float2. The 196KB
//   weight slab is L1-resident (1 CTA/SM). Publishes watermark t+1 per row.
// blockIdx 96..127: simulators, one batch each, 4 neurons/thread, bitmask
//   spike exchange with a 1-byte-per-warp summary, ONE barrier per step.
__global__ void __launch_bounds__(TPB, 1)
fused_k(const int* __restrict__ ct, float* __restrict__ out) {
    const int blk  = blockIdx.x;
    const int tid  = threadIdx.x;
    const int wid  = tid >> 5, lane = tid & 31;

    // ==================== PRODUCER ROLE ====================
    if (blk < NPROD) {
        if (wid >= 8) return;                  // wavefront-bound; extra warps idle
        const int tau = blk >> 2, g = blk & 3;
        const int b   = g * 8 + wid;
        const char* __restrict__ Wc =
            (const char*)d_WFsc + (size_t)(tau * FCOLS + lane * 2) * 4;
        float* __restrict__ dst = d_IF + (size_t)b * TT * NN + tau * FCOLS + lane * 2;

        for (int t = 0; t < TT; t++) {
            int bt = b * TT + t;
            int fc = d_ffcnt[bt];
            const int* __restrict__ lst = d_fflist[bt];
            float a0 = 0.f, a1 = 0.f, a2 = 0.f, a3 = 0.f;
            int e = 0;
#pragma unroll 4
            for (; e + 1 < fc; e += 2) {
                int o0 = lst[e], o1 = lst[e + 1];
                float2 v0 = *(const float2*)(Wc + o0);
                float2 v1 = *(const float2*)(Wc + o1);
                a0 += v0.x; a1 += v0.y; a2 += v1.x; a3 += v1.y;
            }
            if (e < fc) {
                float2 v = *(const float2*)(Wc + lst[e]);
                a0 += v.x; a1 += v.y;
            }
            *(float2*)(dst + (size_t)t * NN) = make_float2(a0 + a2, a1 + a3);
            __syncwarp();
            if (lane == 0) { __threadfence(); __stcg(&d_wm[b][tau], t + 1); }
        }
        return;
    }

    // ==================== SIMULATOR ROLE ====================
    const int b  = blk - NPROD;
    const int n0 = tid * NPT;

    // double-buffered type-split spike bitmasks + per-warp summary bytes
    __shared__ uint4 smA[2][NWARP];
    __shared__ uint4 smB[2][NWARP];
    __shared__ uint4 ssum[2];                  // 12 summary bytes + 4 pad

    if (tid == 0) {
        ssum[0] = make_uint4(0, 0, 0, 0);
        ssum[1] = make_uint4(0, 0, 0, 0);
    }

    int4 ctv = *(const int4*)(ct + n0);
    const int ctk[NPT] = {ctv.x, ctv.y, ctv.z, ctv.w};

    unsigned cA[NPT];                          // static per-warp type masks
#pragma unroll
    for (int k = 0; k < NPT; k++)
        cA[k] = __ballot_sync(0xFFFFFFFFu, ctk[k] == 0);

    float leak[NPT], refstep[NPT];
#pragma unroll
    for (int k = 0; k < NPT; k++) {
        leak[k]    = ctk[k] ? 0.01f : 0.005f;
        refstep[k] = ctk[k] ? 1.0f : 2.0f;
    }
    const u64 leakp[2] = {pk2(leak[0], leak[1]), pk2(leak[2], leak[3])};

    const u64 AR0p = pk2(AR0, AR0), AR1p = pk2(AR1, AR1);
    const u64 AD0p = pk2(AD0, AD0), AD1p = pk2(AD1, AD1), AD2p = pk2(AD2, AD2);
    const u64 HALFp = pk2(0.5f, 0.5f), M70p = pk2(-70.f, -70.f);
    const u64 M65p  = pk2(-65.f, -65.f), TENp = pk2(10.f, 10.f);

    u64 X0[2], X1[2], X2[2], G0[2], G1[2], G2[2], XF[2], GF[2];
    float U[NPT], ref[NPT];
#pragma unroll
    for (int p = 0; p < 2; p++)
        X0[p] = X1[p] = X2[p] = G0[p] = G1[p] = G2[p] = XF[p] = GF[p] = 0ull;
#pragma unroll
    for (int k = 0; k < NPT; k++) { U[k] = -65.0f; ref[k] = 0.f; }

    const char* __restrict__ wb   = (const char*)d_Wsc + (size_t)n0 * 4;
    const float* __restrict__ ifp = d_IF + (size_t)b * TT * NN + n0;
    const size_t VOFF = (size_t)BB * TT * NN;

    // wait for FF rows 0,1 from all 24 tiles; acquire; covers ssum init too
    if (tid < NTILE) {
        while (__ldcg(&d_wm[b][tid]) < 2) __nanosleep(64);
        __threadfence();
    }
    __syncthreads();

    float4 ffcur = __ldcg((const float4*)ifp); // FF drive for t=0

    for (int t = 0; t < TT; t++) {
        const int wp = t & 1, rp = wp ^ 1;

        // prefetch FF drive for t+1 (row readiness guaranteed by watermark)
        float4 ffnext = (t + 1 < TT)
            ? __ldcg((const float4*)(ifp + (size_t)(t + 1) * NN))
            : make_float4(0.f, 0.f, 0.f, 0.f);

        // -------- sparse recurrent gather via bitmasks ----------------------
        float a0 = 0.f, a1 = 0.f, a2 = 0.f, a3 = 0.f;
        float b0 = 0.f, b1 = 0.f, b2 = 0.f, b3 = 0.f;
        {
            uint4 sum = ssum[rp];
            unsigned sw[3] = {sum.x, sum.y, sum.z};
#pragma unroll
            for (int g3 = 0; g3 < 3; g3++) {
                unsigned sb = sw[g3];
                if (sb == 0) continue;                 // uniform branch
                for (int j = 0; j < 4; j++) {
                    unsigned byt = (sb >> (j * 8)) & 0xFFu;
                    if (!byt) continue;
                    int w2 = g3 * 4 + j;
                    if (byt & 0xFu) {
                        uint4 q = smA[rp][w2];
                        unsigned wd[4] = {q.x, q.y, q.z, q.w};
#pragma unroll
                        for (int k = 0; k < 4; k++) {
                            unsigned m = wd[k];
                            while (m) {
                                int i = __ffs(m) - 1; m &= m - 1;
                                const float4 w = *(const float4*)
                                    (wb + (w2 * 128 + i * 4 + k) * (NN * 4));
                                a0 += w.x; a1 += w.y; a2 += w.z; a3 += w.w;
                            }
                        }
                    }
                    if (byt >> 4) {
                        uint4 q = smB[rp][w2];
                        unsigned wd[4] = {q.x, q.y, q.z, q.w};
#pragma unroll
                        for (int k = 0; k < 4; k++) {
                            unsigned m = wd[k];
                            while (m) {
                                int i = __ffs(m) - 1; m &= m - 1;
                                const float4 w = *(const float4*)
                                    (wb + (w2 * 128 + i * 4 + k) * (NN * 4));
                                b0 += w.x; b1 += w.y; b2 += w.z; b3 += w.w;
                            }
                        }
                    }
                }
            }
        }
        const u64 inAp[2] = {pk2(a0, a1), pk2(a2, a3)};
        const u64 inBp[2] = {pk2(b0, b1), pk2(b2, b3)};
        const u64 inFp[2] = {pk2(ffcur.x, ffcur.y), pk2(ffcur.z, ffcur.w)};
        ffcur = ffnext;

        // -------- neuron update (packed filters + membrane) ----------------
        float sv[NPT], uv[NPT];
#pragma unroll
        for (int p = 0; p < 2; p++) {
            X0[p] = fma2(AR0p, X0[p], inAp[p]);
            X1[p] = fma2(AR1p, X1[p], inAp[p]);
            X2[p] = fma2(AR0p, X2[p], inBp[p]);
            G0[p] = fma2(AD0p, G0[p], X0[p]);
            G1[p] = fma2(AD1p, G1[p], X1[p]);
            G2[p] = fma2(AD2p, G2[p], X2[p]);
            XF[p] = fma2(AR0p, XF[p], inFp[p]);
            GF[p] = fma2(AD0p, GF[p], XF[p]);

            u64 gtot = add2(fma2(HALFp, G1[p], G0[p]), add2(G2[p], GF[p]));
            u64 gE   = mul2(M70p, G2[p]);
            float u0 = U[p * 2], u1 = U[p * 2 + 1];
            u64 Up  = pk2(u0, u1);
            u64 nUp = pk2(-u0, -u1);
            u64 Isyn = fma2(gtot, nUp, gE);
            u64 s1   = add2(M65p, nUp);
            u64 s2   = fma2(TENp, s1, Isyn);
            u64 Unp  = fma2(leakp[p], s2, Up);

            float Un0, Un1;
            upk2(Un0, Un1, Unp);
            float Unk[2] = {Un0, Un1};
#pragma unroll
            for (int q = 0; q < 2; q++) {
                int k = p * 2 + q;
                float Un = Unk[q];
                if (ref[k] > 0.0f) Un = -65.0f;      // refractory clamp
                ref[k] = fmaxf(ref[k] - 1.0f, 0.0f);
                float s = ((Un + 50.0f) >= 0.0f) ? 1.0f : 0.0f;
                if (s > 0.0f) { Un = -65.0f; ref[k] = refstep[k]; }
                U[k] = Un;
                sv[k] = s;
                uv[k] = Un;
            }
        }

        // outputs: spikes then volts, both (B,T,N)
        size_t o = ((size_t)b * TT + t) * NN + n0;
        *(float4*)(out + o)        = make_float4(sv[0], sv[1], sv[2], sv[3]);
        *(float4*)(out + VOFF + o) = make_float4(uv[0], uv[1], uv[2], uv[3]);

        // -------- spike bitmask publication ---------------------------------
        unsigned A[4], Bm[4], nz = 0;
#pragma unroll
        for (int k = 0; k < NPT; k++) {
            unsigned mk = __ballot_sync(0xFFFFFFFFu, sv[k] > 0.0f);
            A[k]  = mk & cA[k];
            Bm[k] = mk & ~cA[k];
            nz |= (A[k]  ? 1u : 0u) << k;
            nz |= (Bm[k] ? 1u : 0u) << (k + 4);
        }
        if (lane == 0) {
            smA[wp][wid] = make_uint4(A[0], A[1], A[2], A[3]);
            smB[wp][wid] = make_uint4(Bm[0], Bm[1], Bm[2], Bm[3]);
            ((unsigned char*)&ssum[wp])[wid] = (unsigned char)nz;
        }

        // -------- periodic FF watermark check (amortized) -------------------
        if ((t & 7) == 0 && tid < NTILE) {
            int target = (t + 10 < TT) ? (t + 10) : TT;
            while (__ldcg(&d_wm[b][tid]) < target) __nanosleep(64);
            __threadfence();
        }
        __syncthreads();                       // the ONE barrier per step
    }
}

// ------------------------- launcher -----------------------------------------
extern "C" void kernel_launch(void* const* d_in, const int* in_sizes, int n_in,
                              void* d_out, int out_size) {
    const float* input_spikes = (const float*)d_in[0]; // (B,T,NI)
    const float* weights      = (const float*)d_in[1]; // (NN,NN)
    const float* weights_FF   = (const float*)d_in[2]; // (NI,NN)
    const float* sf           = (const float*)d_in[3]; // (2,2)
    const float* sff          = (const float*)d_in[4]; // (1,2)
    const int*   ct           = (const int*)d_in[5];   // (NN,)
    (void)in_sizes; (void)n_in; (void)out_size;

    init_k<<<1, BB * NTILE>>>();
    int total = NN * NN + NI * NN;
    scale_k<<<(total + 255) / 256, 256>>>(weights, weights_FF, sf, sff, ct);
    ffl_k<<<BB * TT / 4, 128>>>(input_spikes);
    fused_k<<<NPROD + BB, TPB>>>(ct, (float*)d_out);
}

// round 8
// speedup vs baseline: 3.0760x; 3.0760x over previous
#include <cuda_runtime.h>
#include <cstdint>

// Problem constants (fixed by the reference)
#define BB 32
#define TT 256
#define NN 1536
#define NI 768

// Sim config: ONE CTA per batch, 384 threads, 4 neurons/thread.
#define TPB   384
#define NPT   4
#define NWARP (TPB / 32)

// exp constants, correctly rounded fp32
#define AR0 0.13533528323661270f   // exp(-2)    : rise tau 0.5 (syn0, syn2, FF)
#define AR1 0.60653065971263342f   // exp(-0.5)  : rise tau 2   (syn1)
#define AD0 0.60653065971263342f   // exp(-0.5)  : decay tau 2  (syn0, FF)
#define AD1 0.99004983374916805f   // exp(-0.01) : decay tau 100(syn1)
#define AD2 0.81873075307798186f   // exp(-0.2)  : decay tau 5  (syn2)

// ------------------------- device scratch (statics; no allocs) -------------
__device__ float d_Wsc[NN * NN];             // weights * sf[ct[n]][ct[m]]
__device__ float d_WFsc[NI * NN];            // weights_FF * sfF[ct[m]]
__device__ float d_IF[(size_t)BB * TT * NN]; // precomputed FF drive
__device__ int   d_ffcnt[BB * TT];           // input spike counts per (b,t)
__device__ int   d_fflist[BB * TT][NI];      // byte offsets j*NN*4

// ------------------------- packed f32x2 helpers -----------------------------
typedef unsigned long long u64;
__device__ __forceinline__ u64 pk2(float lo, float hi) {
    u64 r; asm("mov.b64 %0, {%1,%2};" : "=l"(r) : "f"(lo), "f"(hi)); return r;
}
__device__ __forceinline__ void upk2(float& lo, float& hi, u64 v) {
    asm("mov.b64 {%0,%1}, %2;" : "=f"(lo), "=f"(hi) : "l"(v));
}
__device__ __forceinline__ u64 fma2(u64 a, u64 b, u64 c) {
    u64 d; asm("fma.rn.f32x2 %0, %1, %2, %3;" : "=l"(d) : "l"(a), "l"(b), "l"(c));
    return d;
}
__device__ __forceinline__ u64 add2(u64 a, u64 b) {
    u64 d; asm("add.rn.f32x2 %0, %1, %2;" : "=l"(d) : "l"(a), "l"(b)); return d;
}
__device__ __forceinline__ u64 mul2(u64 a, u64 b) {
    u64 d; asm("mul.rn.f32x2 %0, %1, %2;" : "=l"(d) : "l"(a), "l"(b)); return d;
}

// ------------------------- weight scaling ----------------------------------
__global__ void scale_k(const float* __restrict__ w, const float* __restrict__ wff,
                        const float* __restrict__ sf, const float* __restrict__ sff,
                        const int* __restrict__ ct) {
    int idx = blockIdx.x * 256 + threadIdx.x;
    if (idx < NN * NN) {
        int n = idx / NN, m = idx % NN;
        d_Wsc[idx] = w[idx] * sf[ct[n] * 2 + ct[m]];
    } else {
        int r = idx - NN * NN;
        if (r < NI * NN) {
            int m = r % NN;
            d_WFsc[r] = wff[r] * sff[ct[m]];   // ct_FF is all zeros -> row 0
        }
    }
}

// ------------------------- FF spike lists (ballot-ordered, byte offsets) ---
__global__ void ffl_k(const float* __restrict__ inp) {
    int bt = blockIdx.x * 4 + (threadIdx.x >> 5); // 4 (b,t) rows per block
    int lane = threadIdx.x & 31;
    const float* row = inp + (size_t)bt * NI;
    int cnt = 0;
    for (int base = 0; base < NI; base += 32) {
        float v = row[base + lane];
        unsigned m = __ballot_sync(0xFFFFFFFFu, v > 0.5f);
        if (v > 0.5f) {
            int p = cnt + __popc(m & ((1u << lane) - 1u));
            d_fflist[bt][p] = (base + lane) * NN * 4;   // byte offset of row
        }
        cnt += __popc(m);
    }
    if (lane == 0) d_ffcnt[bt] = cnt;
}

// ------------------------- FF drive precompute ------------------------------
// Grid = (batch, 64-col tile), batch fastest: the 3 co-resident CTAs per SM
// share the SAME 196KB L1-resident column slab. 16 warps, each warp owns 16
// timesteps; lanes cover 2 cols each (float2).
#define FCOLS 64
#define FTPB  512
__global__ void __launch_bounds__(FTPB, 3) ffpre_k() {
    int b  = blockIdx.x;
    int c0 = blockIdx.y * FCOLS;
    int w    = threadIdx.x >> 5;
    int lane = threadIdx.x & 31;
    const char* __restrict__ Wc =
        (const char*)d_WFsc + (size_t)(c0 + lane * 2) * 4;
#pragma unroll
    for (int ti = 0; ti < TT / 16; ti++) {
        int t  = w * 16 + ti;
        int bt = b * TT + t;
        int fc = d_ffcnt[bt];
        const int* __restrict__ lst = d_fflist[bt];
        float a0 = 0.f, a1 = 0.f, a2 = 0.f, a3 = 0.f;
        int e = 0;
#pragma unroll 4
        for (; e + 1 < fc; e += 2) {
            int o0 = lst[e], o1 = lst[e + 1];
            float2 v0 = *(const float2*)(Wc + o0);
            float2 v1 = *(const float2*)(Wc + o1);
            a0 += v0.x; a1 += v0.y; a2 += v1.x; a3 += v1.y;
        }
        if (e < fc) {
            float2 v = *(const float2*)(Wc + lst[e]);
            a0 += v.x; a1 += v.y;
        }
        *(float2*)&d_IF[(size_t)bt * NN + c0 + lane * 2] =
            make_float2(a0 + a2, a1 + a3);
    }
}

// ------------------------- main persistent simulator ------------------------
// grid = 32 (one CTA per batch), block = 384 (one thread per 4 neurons).
// Spike exchange via double-buffered type-split BITMASKS (2x uint4 per warp)
// plus a per-warp 1-byte nonzero summary -> ONE __syncthreads per step,
// no prefix scan. Bit i of mask word k of warp w2 <-> neuron w2*128 + i*4 + k.
__global__ void __launch_bounds__(TPB, 1)
sim_k(const int* __restrict__ ct, float* __restrict__ out) {
    const int b    = blockIdx.x;
    const int tid  = threadIdx.x;
    const int wid  = tid >> 5, lane = tid & 31;
    const int n0   = tid * NPT;

    __shared__ uint4 smA[2][NWARP];
    __shared__ uint4 smB[2][NWARP];
    __shared__ uint4 ssum[2];                  // 12 summary bytes + 4 pad

    if (tid == 0) {
        ssum[0] = make_uint4(0, 0, 0, 0);
        ssum[1] = make_uint4(0, 0, 0, 0);
    }

    int4 ctv = *(const int4*)(ct + n0);
    const int ctk[NPT] = {ctv.x, ctv.y, ctv.z, ctv.w};

    unsigned cA[NPT];                          // static per-warp type masks
#pragma unroll
    for (int k = 0; k < NPT; k++)
        cA[k] = __ballot_sync(0xFFFFFFFFu, ctk[k] == 0);

    float leak[NPT], refstep[NPT];
#pragma unroll
    for (int k = 0; k < NPT; k++) {
        leak[k]    = ctk[k] ? 0.01f : 0.005f;
        refstep[k] = ctk[k] ? 1.0f : 2.0f;
    }
    const u64 leakp[2] = {pk2(leak[0], leak[1]), pk2(leak[2], leak[3])};

    const u64 AR0p = pk2(AR0, AR0), AR1p = pk2(AR1, AR1);
    const u64 AD0p = pk2(AD0, AD0), AD1p = pk2(AD1, AD1), AD2p = pk2(AD2, AD2);
    const u64 HALFp = pk2(0.5f, 0.5f), M70p = pk2(-70.f, -70.f);
    const u64 M65p  = pk2(-65.f, -65.f), TENp = pk2(10.f, 10.f);

    u64 X0[2], X1[2], X2[2], G0[2], G1[2], G2[2], XF[2], GF[2];
    float U[NPT], ref[NPT];
#pragma unroll
    for (int p = 0; p < 2; p++)
        X0[p] = X1[p] = X2[p] = G0[p] = G1[p] = G2[p] = XF[p] = GF[p] = 0ull;
#pragma unroll
    for (int k = 0; k < NPT; k++) { U[k] = -65.0f; ref[k] = 0.f; }

    const char* __restrict__ wb   = (const char*)d_Wsc + (size_t)n0 * 4;
    const float* __restrict__ ifp = d_IF + (size_t)b * TT * NN + n0;
    const size_t VOFF = (size_t)BB * TT * NN;

    float4 ffcur = __ldcg((const float4*)ifp); // FF drive for t=0
    __syncthreads();                           // ssum init visible

    for (int t = 0; t < TT; t++) {
        const int wp = t & 1, rp = wp ^ 1;

        // prefetch FF drive for t+1 (hides DRAM latency behind this step)
        float4 ffnext = (t + 1 < TT)
            ? __ldcg((const float4*)(ifp + (size_t)(t + 1) * NN))
            : make_float4(0.f, 0.f, 0.f, 0.f);

        // -------- sparse recurrent gather via bitmasks ----------------------
        float a0 = 0.f, a1 = 0.f, a2 = 0.f, a3 = 0.f;
        float b0 = 0.f, b1 = 0.f, b2 = 0.f, b3 = 0.f;
        {
            uint4 sum = ssum[rp];
            unsigned sw[3] = {sum.x, sum.y, sum.z};
#pragma unroll
            for (int g3 = 0; g3 < 3; g3++) {
                unsigned sb = sw[g3];
                if (sb == 0) continue;                 // uniform branch
                for (int j = 0; j < 4; j++) {
                    unsigned byt = (sb >> (j * 8)) & 0xFFu;
                    if (!byt) continue;
                    int w2 = g3 * 4 + j;
                    if (byt & 0xFu) {
                        uint4 q = smA[rp][w2];
                        unsigned wd[4] = {q.x, q.y, q.z, q.w};
#pragma unroll
                        for (int k = 0; k < 4; k++) {
                            unsigned m = wd[k];
                            while (m) {
                                int i = __ffs(m) - 1; m &= m - 1;
                                const float4 w = *(const float4*)
                                    (wb + (w2 * 128 + i * 4 + k) * (NN * 4));
                                a0 += w.x; a1 += w.y; a2 += w.z; a3 += w.w;
                            }
                        }
                    }
                    if (byt >> 4) {
                        uint4 q = smB[rp][w2];
                        unsigned wd[4] = {q.x, q.y, q.z, q.w};
#pragma unroll
                        for (int k = 0; k < 4; k++) {
                            unsigned m = wd[k];
                            while (m) {
                                int i = __ffs(m) - 1; m &= m - 1;
                                const float4 w = *(const float4*)
                                    (wb + (w2 * 128 + i * 4 + k) * (NN * 4));
                                b0 += w.x; b1 += w.y; b2 += w.z; b3 += w.w;
                            }
                        }
                    }
                }
            }
        }
        const u64 inAp[2] = {pk2(a0, a1), pk2(a2, a3)};
        const u64 inBp[2] = {pk2(b0, b1), pk2(b2, b3)};
        const u64 inFp[2] = {pk2(ffcur.x, ffcur.y), pk2(ffcur.z, ffcur.w)};
        ffcur = ffnext;

        // -------- neuron update (packed filters + membrane) ----------------
        float sv[NPT], uv[NPT];
#pragma unroll
        for (int p = 0; p < 2; p++) {
            X0[p] = fma2(AR0p, X0[p], inAp[p]);
            X1[p] = fma2(AR1p, X1[p], inAp[p]);
            X2[p] = fma2(AR0p, X2[p], inBp[p]);
            G0[p] = fma2(AD0p, G0[p], X0[p]);
            G1[p] = fma2(AD1p, G1[p], X1[p]);
            G2[p] = fma2(AD2p, G2[p], X2[p]);
            XF[p] = fma2(AR0p, XF[p], inFp[p]);
            GF[p] = fma2(AD0p, GF[p], XF[p]);

            u64 gtot = add2(fma2(HALFp, G1[p], G0[p]), add2(G2[p], GF[p]));
            u64 gE   = mul2(M70p, G2[p]);
            float u0 = U[p * 2], u1 = U[p * 2 + 1];
            u64 Up  = pk2(u0, u1);
            u64 nUp = pk2(-u0, -u1);
            u64 Isyn = fma2(gtot, nUp, gE);
            u64 s1   = add2(M65p, nUp);
            u64 s2   = fma2(TENp, s1, Isyn);
            u64 Unp  = fma2(leakp[p], s2, Up);

            float Un0, Un1;
            upk2(Un0, Un1, Unp);
            float Unk[2] = {Un0, Un1};
#pragma unroll
            for (int q = 0; q < 2; q++) {
                int k = p * 2 + q;
                float Un = Unk[q];
                if (ref[k] > 0.0f) Un = -65.0f;      // refractory clamp
                ref[k] = fmaxf(ref[k] - 1.0f, 0.0f);
                float s = ((Un + 50.0f) >= 0.0f) ? 1.0f : 0.0f;
                if (s > 0.0f) { Un = -65.0f; ref[k] = refstep[k]; }
                U[k] = Un;
                sv[k] = s;
                uv[k] = Un;
            }
        }

        // outputs: spikes then volts, both (B,T,N)
        size_t o = ((size_t)b * TT + t) * NN + n0;
        *(float4*)(out + o)        = make_float4(sv[0], sv[1], sv[2], sv[3]);
        *(float4*)(out + VOFF + o) = make_float4(uv[0], uv[1], uv[2], uv[3]);

        // -------- spike bitmask publication ---------------------------------
        unsigned A[4], Bm[4], nz = 0;
#pragma unroll
        for (int k = 0; k < NPT; k++) {
            unsigned mk = __ballot_sync(0xFFFFFFFFu, sv[k] > 0.0f);
            A[k]  = mk & cA[k];
            Bm[k] = mk & ~cA[k];
            nz |= (A[k]  ? 1u : 0u) << k;
            nz |= (Bm[k] ? 1u : 0u) << (k + 4);
        }
        if (lane == 0) {
            smA[wp][wid] = make_uint4(A[0], A[1], A[2], A[3]);
            smB[wp][wid] = make_uint4(Bm[0], Bm[1], Bm[2], Bm[3]);
            ((unsigned char*)&ssum[wp])[wid] = (unsigned char)nz;
        }
        __syncthreads();                       // the ONE barrier per step
    }
}

// ------------------------- launcher -----------------------------------------
extern "C" void kernel_launch(void* const* d_in, const int* in_sizes, int n_in,
                              void* d_out, int out_size) {
    const float* input_spikes = (const float*)d_in[0]; // (B,T,NI)
    const float* weights      = (const float*)d_in[1]; // (NN,NN)
    const float* weights_FF   = (const float*)d_in[2]; // (NI,NN)
    const float* sf           = (const float*)d_in[3]; // (2,2)
    const float* sff          = (const float*)d_in[4]; // (1,2)
    const int*   ct           = (const int*)d_in[5];   // (NN,)
    (void)in_sizes; (void)n_in; (void)out_size;

    int total = NN * NN + NI * NN;
    scale_k<<<(total + 255) / 256, 256>>>(weights, weights_FF, sf, sff, ct);
    ffl_k<<<BB * TT / 4, 128>>>(input_spikes);
    ffpre_k<<<dim3(BB, NN / FCOLS), FTPB>>>();
    sim_k<<<BB, TPB>>>(ct, (float*)d_out);
}

// round 9
// speedup vs baseline: 3.1585x; 1.0268x over previous
#include <cuda_runtime.h>
#include <cstdint>

// Problem constants (fixed by the reference)
#define BB 32
#define TT 256
#define NN 1536
#define NI 768

// Sim config: ONE CTA per batch, 384 threads, 4 neurons/thread.
#define TPB   384
#define NPT   4
#define NWARP (TPB / 32)

// exp constants, correctly rounded fp32
#define AR0 0.13533528323661270f   // exp(-2)    : rise tau 0.5 (syn0, syn2, FF)
#define AR1 0.60653065971263342f   // exp(-0.5)  : rise tau 2   (syn1)
#define AD0 0.60653065971263342f   // exp(-0.5)  : decay tau 2  (syn0, FF)
#define AD1 0.99004983374916805f   // exp(-0.01) : decay tau 100(syn1)
#define AD2 0.81873075307798186f   // exp(-0.2)  : decay tau 5  (syn2)

// ------------------------- device scratch (statics; no allocs) -------------
__device__ float d_Wsc[NN * NN];             // weights * sf[ct[n]][ct[m]]
__device__ float d_WFsc[NI * NN];            // weights_FF * sfF[ct[m]]
__device__ float d_IF[(size_t)BB * TT * NN]; // precomputed FF drive
__device__ int   d_ffcnt[BB * TT];           // input spike counts per (b,t)
__device__ int   d_fflist[BB * TT][NI];      // byte offsets j*NN*4

// ------------------------- packed f32x2 helpers -----------------------------
typedef unsigned long long u64;
__device__ __forceinline__ u64 pk2(float lo, float hi) {
    u64 r; asm("mov.b64 %0, {%1,%2};" : "=l"(r) : "f"(lo), "f"(hi)); return r;
}
__device__ __forceinline__ void upk2(float& lo, float& hi, u64 v) {
    asm("mov.b64 {%0,%1}, %2;" : "=f"(lo), "=f"(hi) : "l"(v));
}
__device__ __forceinline__ u64 fma2(u64 a, u64 b, u64 c) {
    u64 d; asm("fma.rn.f32x2 %0, %1, %2, %3;" : "=l"(d) : "l"(a), "l"(b), "l"(c));
    return d;
}
__device__ __forceinline__ u64 add2(u64 a, u64 b) {
    u64 d; asm("add.rn.f32x2 %0, %1, %2;" : "=l"(d) : "l"(a), "l"(b)); return d;
}
__device__ __forceinline__ u64 mul2(u64 a, u64 b) {
    u64 d; asm("mul.rn.f32x2 %0, %1, %2;" : "=l"(d) : "l"(a), "l"(b)); return d;
}

// ------------------------- weight scaling (float4 vectorized) ---------------
__global__ void scale_k(const float4* __restrict__ w, const float4* __restrict__ wff,
                        const float* __restrict__ sf, const float* __restrict__ sff,
                        const int* __restrict__ ct) {
    const int T4 = (NN * NN) / 4;
    const int F4 = (NI * NN) / 4;
    int idx = blockIdx.x * 256 + threadIdx.x;
    if (idx < T4) {
        int i4 = idx * 4;
        int n = i4 / NN, m = i4 % NN;
        int4 cm = *(const int4*)(ct + m);
        int cn = ct[n] * 2;
        float4 v = w[idx];
        v.x *= sf[cn + cm.x];
        v.y *= sf[cn + cm.y];
        v.z *= sf[cn + cm.z];
        v.w *= sf[cn + cm.w];
        *(float4*)&d_Wsc[i4] = v;
    } else if (idx < T4 + F4) {
        int r = idx - T4;
        int i4 = r * 4;
        int m = i4 % NN;
        int4 cm = *(const int4*)(ct + m);
        float4 v = wff[r];
        v.x *= sff[cm.x];
        v.y *= sff[cm.y];
        v.z *= sff[cm.z];
        v.w *= sff[cm.w];
        *(float4*)&d_WFsc[i4] = v;
    }
}

// ------------------------- FF spike lists (ballot-ordered, byte offsets) ---
__global__ void ffl_k(const float* __restrict__ inp) {
    int bt = blockIdx.x * 4 + (threadIdx.x >> 5); // 4 (b,t) rows per block
    int lane = threadIdx.x & 31;
    const float* row = inp + (size_t)bt * NI;
    int cnt = 0;
    for (int base = 0; base < NI; base += 32) {
        float v = row[base + lane];
        unsigned m = __ballot_sync(0xFFFFFFFFu, v > 0.5f);
        if (v > 0.5f) {
            int p = cnt + __popc(m & ((1u << lane) - 1u));
            d_fflist[bt][p] = (base + lane) * NN * 4;   // byte offset of row
        }
        cnt += __popc(m);
    }
    if (lane == 0) d_ffcnt[bt] = cnt;
}

// ------------------------- FF drive precompute ------------------------------
// Grid = (batch, 64-col tile), batch fastest: the 3 co-resident CTAs per SM
// share the SAME 196KB L1-resident column slab. 16 warps, each warp owns 16
// timesteps; lanes cover 2 cols each, accumulated packed (f32x2).
// Even/odd accumulator grouping matches prior rounds bit-exactly.
#define FCOLS 64
#define FTPB  512
__global__ void __launch_bounds__(FTPB, 3) ffpre_k() {
    int b  = blockIdx.x;
    int c0 = blockIdx.y * FCOLS;
    int w    = threadIdx.x >> 5;
    int lane = threadIdx.x & 31;
    const char* __restrict__ Wc =
        (const char*)d_WFsc + (size_t)(c0 + lane * 2) * 4;
#pragma unroll
    for (int ti = 0; ti < TT / 16; ti++) {
        int t  = w * 16 + ti;
        int bt = b * TT + t;
        int fc = d_ffcnt[bt];
        const int* __restrict__ lst = d_fflist[bt];
        u64 aE = 0ull, aO = 0ull;
        int e = 0;
#pragma unroll 8
        for (; e + 1 < fc; e += 2) {
            u64 w0 = *(const u64*)(Wc + lst[e]);
            u64 w1 = *(const u64*)(Wc + lst[e + 1]);
            aE = add2(aE, w0);
            aO = add2(aO, w1);
        }
        if (e < fc) aE = add2(aE, *(const u64*)(Wc + lst[e]));
        u64 s = add2(aE, aO);
        float lo, hi;
        upk2(lo, hi, s);
        *(float2*)&d_IF[(size_t)bt * NN + c0 + lane * 2] = make_float2(lo, hi);
    }
}

// ------------------------- main persistent simulator ------------------------
// grid = 32 (one CTA per batch), block = 384 (one thread per 4 neurons).
// Spike exchange via double-buffered type-split BITMASKS (2x uint4 per warp)
// plus a per-warp 1-byte nonzero summary -> ONE __syncthreads per step.
// Gather accumulates packed f32x2 directly into the update's input registers.
// Bit i of mask word k of warp w2 <-> neuron w2*128 + i*4 + k.
__global__ void __launch_bounds__(TPB, 1)
sim_k(const int* __restrict__ ct, float* __restrict__ out) {
    const int b    = blockIdx.x;
    const int tid  = threadIdx.x;
    const int wid  = tid >> 5, lane = tid & 31;
    const int n0   = tid * NPT;

    __shared__ uint4 smA[2][NWARP];
    __shared__ uint4 smB[2][NWARP];
    __shared__ uint4 ssum[2];                  // 12 summary bytes + 4 pad

    if (tid == 0) {
        ssum[0] = make_uint4(0, 0, 0, 0);
        ssum[1] = make_uint4(0, 0, 0, 0);
    }

    int4 ctv = *(const int4*)(ct + n0);
    const int ctk[NPT] = {ctv.x, ctv.y, ctv.z, ctv.w};

    unsigned cA[NPT];                          // static per-warp type masks
#pragma unroll
    for (int k = 0; k < NPT; k++)
        cA[k] = __ballot_sync(0xFFFFFFFFu, ctk[k] == 0);

    float leak[NPT], refstep[NPT];
#pragma unroll
    for (int k = 0; k < NPT; k++) {
        leak[k]    = ctk[k] ? 0.01f : 0.005f;
        refstep[k] = ctk[k] ? 1.0f : 2.0f;
    }
    const u64 leakp[2] = {pk2(leak[0], leak[1]), pk2(leak[2], leak[3])};

    const u64 AR0p = pk2(AR0, AR0), AR1p = pk2(AR1, AR1);
    const u64 AD0p = pk2(AD0, AD0), AD1p = pk2(AD1, AD1), AD2p = pk2(AD2, AD2);
    const u64 HALFp = pk2(0.5f, 0.5f), M70p = pk2(-70.f, -70.f);
    const u64 M65p  = pk2(-65.f, -65.f), TENp = pk2(10.f, 10.f);

    u64 X0[2], X1[2], X2[2], G0[2], G1[2], G2[2], XF[2], GF[2];
    float U[NPT], ref[NPT];
#pragma unroll
    for (int p = 0; p < 2; p++)
        X0[p] = X1[p] = X2[p] = G0[p] = G1[p] = G2[p] = XF[p] = GF[p] = 0ull;
#pragma unroll
    for (int k = 0; k < NPT; k++) { U[k] = -65.0f; ref[k] = 0.f; }

    const char* __restrict__ wb   = (const char*)d_Wsc + (size_t)n0 * 4;
    const float* __restrict__ ifp = d_IF + (size_t)b * TT * NN + n0;
    const size_t VOFF = (size_t)BB * TT * NN;

    float4 ffcur = __ldcg((const float4*)ifp); // FF drive for t=0
    __syncthreads();                           // ssum init visible

    for (int t = 0; t < TT; t++) {
        const int wp = t & 1, rp = wp ^ 1;

        // prefetch FF drive for t+1 (hides DRAM latency behind this step)
        float4 ffnext = (t + 1 < TT)
            ? __ldcg((const float4*)(ifp + (size_t)(t + 1) * NN))
            : make_float4(0.f, 0.f, 0.f, 0.f);

        // -------- sparse recurrent gather via bitmasks (packed adds) --------
        u64 aA01 = 0ull, aA23 = 0ull, aB01 = 0ull, aB23 = 0ull;
        {
            uint4 sum = ssum[rp];
            unsigned sw[3] = {sum.x, sum.y, sum.z};
#pragma unroll
            for (int g3 = 0; g3 < 3; g3++) {
                unsigned sb = sw[g3];
                if (sb == 0) continue;                 // uniform branch
                for (int j = 0; j < 4; j++) {
                    unsigned byt = (sb >> (j * 8)) & 0xFFu;
                    if (!byt) continue;
                    int w2 = g3 * 4 + j;
                    const char* wbase = wb + (size_t)w2 * (128 * NN * 4);
                    if (byt & 0xFu) {
                        uint4 q = smA[rp][w2];
                        unsigned wd[4] = {q.x, q.y, q.z, q.w};
#pragma unroll
                        for (int k = 0; k < 4; k++) {
                            unsigned m = wd[k];
                            const char* kb = wbase + k * (NN * 4);
                            while (m) {
                                int i = __ffs(m) - 1; m &= m - 1;
                                ulonglong2 ww = *(const ulonglong2*)
                                    (kb + i * (4 * NN * 4));
                                aA01 = add2(aA01, ww.x);
                                aA23 = add2(aA23, ww.y);
                            }
                        }
                    }
                    if (byt >> 4) {
                        uint4 q = smB[rp][w2];
                        unsigned wd[4] = {q.x, q.y, q.z, q.w};
#pragma unroll
                        for (int k = 0; k < 4; k++) {
                            unsigned m = wd[k];
                            const char* kb = wbase + k * (NN * 4);
                            while (m) {
                                int i = __ffs(m) - 1; m &= m - 1;
                                ulonglong2 ww = *(const ulonglong2*)
                                    (kb + i * (4 * NN * 4));
                                aB01 = add2(aB01, ww.x);
                                aB23 = add2(aB23, ww.y);
                            }
                        }
                    }
                }
            }
        }
        const u64 inAp[2] = {aA01, aA23};
        const u64 inBp[2] = {aB01, aB23};
        const u64 inFp[2] = {pk2(ffcur.x, ffcur.y), pk2(ffcur.z, ffcur.w)};
        ffcur = ffnext;

        // -------- neuron update (packed filters + membrane) ----------------
        float sv[NPT], uv[NPT];
#pragma unroll
        for (int p = 0; p < 2; p++) {
            X0[p] = fma2(AR0p, X0[p], inAp[p]);
            X1[p] = fma2(AR1p, X1[p], inAp[p]);
            X2[p] = fma2(AR0p, X2[p], inBp[p]);
            G0[p] = fma2(AD0p, G0[p], X0[p]);
            G1[p] = fma2(AD1p, G1[p], X1[p]);
            G2[p] = fma2(AD2p, G2[p], X2[p]);
            XF[p] = fma2(AR0p, XF[p], inFp[p]);
            GF[p] = fma2(AD0p, GF[p], XF[p]);

            u64 gtot = add2(fma2(HALFp, G1[p], G0[p]), add2(G2[p], GF[p]));
            u64 gE   = mul2(M70p, G2[p]);
            float u0 = U[p * 2], u1 = U[p * 2 + 1];
            u64 Up  = pk2(u0, u1);
            u64 nUp = pk2(-u0, -u1);
            u64 Isyn = fma2(gtot, nUp, gE);
            u64 s1   = add2(M65p, nUp);
            u64 s2   = fma2(TENp, s1, Isyn);
            u64 Unp  = fma2(leakp[p], s2, Up);

            float Un0, Un1;
            upk2(Un0, Un1, Unp);
            float Unk[2] = {Un0, Un1};
#pragma unroll
            for (int q = 0; q < 2; q++) {
                int k = p * 2 + q;
                float Un = Unk[q];
                if (ref[k] > 0.0f) Un = -65.0f;      // refractory clamp
                ref[k] = fmaxf(ref[k] - 1.0f, 0.0f);
                float s = ((Un + 50.0f) >= 0.0f) ? 1.0f : 0.0f;
                if (s > 0.0f) { Un = -65.0f; ref[k] = refstep[k]; }
                U[k] = Un;
                sv[k] = s;
                uv[k] = Un;
            }
        }

        // outputs: spikes then volts, both (B,T,N)
        size_t o = ((size_t)b * TT + t) * NN + n0;
        *(float4*)(out + o)        = make_float4(sv[0], sv[1], sv[2], sv[3]);
        *(float4*)(out + VOFF + o) = make_float4(uv[0], uv[1], uv[2], uv[3]);

        // -------- spike bitmask publication ---------------------------------
        unsigned A[4], Bm[4], nz = 0;
#pragma unroll
        for (int k = 0; k < NPT; k++) {
            unsigned mk = __ballot_sync(0xFFFFFFFFu, sv[k] > 0.0f);
            A[k]  = mk & cA[k];
            Bm[k] = mk & ~cA[k];
            nz |= (A[k]  ? 1u : 0u) << k;
            nz |= (Bm[k] ? 1u : 0u) << (k + 4);
        }
        if (lane == 0) {
            smA[wp][wid] = make_uint4(A[0], A[1], A[2], A[3]);
            smB[wp][wid] = make_uint4(Bm[0], Bm[1], Bm[2], Bm[3]);
            ((unsigned char*)&ssum[wp])[wid] = (unsigned char)nz;
        }
        __syncthreads();                       // the ONE barrier per step
    }
}

// ------------------------- launcher -----------------------------------------
extern "C" void kernel_launch(void* const* d_in, const int* in_sizes, int n_in,
                              void* d_out, int out_size) {
    const float* input_spikes = (const float*)d_in[0]; // (B,T,NI)
    const float* weights      = (const float*)d_in[1]; // (NN,NN)
    const float* weights_FF   = (const float*)d_in[2]; // (NI,NN)
    const float* sf           = (const float*)d_in[3]; // (2,2)
    const float* sff          = (const float*)d_in[4]; // (1,2)
    const int*   ct           = (const int*)d_in[5];   // (NN,)
    (void)in_sizes; (void)n_in; (void)out_size;

    int total4 = (NN * NN + NI * NN) / 4;
    scale_k<<<(total4 + 255) / 256, 256>>>((const float4*)weights,
                                           (const float4*)weights_FF,
                                           sf, sff, ct);
    ffl_k<<<BB * TT / 4, 128>>>(input_spikes);
    ffpre_k<<<dim3(BB, NN / FCOLS), FTPB>>>();
    sim_k<<<BB, TPB>>>(ct, (float*)d_out);
}